// round 2
// baseline (speedup 1.0000x reference)
#include <cuda_runtime.h>
#include <math.h>

// Problem constants (fixed by the reference: B=16, N=4096, Z=128)
#define BB 16
#define NN 4096
#define ZZ 128

#define THREADS 256
#define Q 4                      // queries per thread (register-blocked)
#define CHUNK 1024               // opponents staged in smem per phase (32KB duplicated)
#define QTILE (THREADS * Q)      // 1024 queries per CTA
#define XTILES (NN / QTILE)      // 4
#define NCTAS (XTILES * BB * 2)  // 128

__device__ float g_partials[NCTAS];
__device__ int   g_count = 0;

// ---- packed f32x2 helpers (Blackwell FFMA2 path) ----
__device__ __forceinline__ unsigned long long ffma2(unsigned long long a,
                                                    unsigned long long b,
                                                    unsigned long long c) {
    unsigned long long d;
    asm("fma.rn.f32x2 %0, %1, %2, %3;" : "=l"(d) : "l"(a), "l"(b), "l"(c));
    return d;
}
__device__ __forceinline__ unsigned long long pack2(float lo, float hi) {
    unsigned long long d;
    asm("mov.b64 %0, {%1, %2};" : "=l"(d) : "f"(lo), "f"(hi));
    return d;
}
__device__ __forceinline__ void min2(float& m0, float& m1, unsigned long long t) {
    float lo, hi;
    asm("mov.b64 {%0, %1}, %2;" : "=f"(lo), "=f"(hi) : "l"(t));
    m0 = fminf(m0, lo);
    m1 = fminf(m1, hi);
}

// Each CTA: one (batch, direction, query-tile). Thread owns Q=4 queries
// (packed as two f32x2 pairs), sweeps all 4096 opponents from smem.
// Opponent stored DUPLICATED: {-2x,-2x},{-2y,-2y},{-2z,-2z},{w,w} so the
// candidate distance for a query pair is exactly 3 packed FFMA2 with zero
// packing MOVs in the hot loop. The query-norm term is added once per query
// at the end; across both directions this reconstructs the full Chamfer sum.
// The LAST CTA (atomic ticket) also folds in the KL term and writes out[0],
// eliminating the second kernel launch.
__global__ __launch_bounds__(THREADS)
void chamfer_kernel(const float* __restrict__ preds,
                    const float* __restrict__ gts,
                    const float* __restrict__ mu,
                    const float* __restrict__ logvar,
                    float* __restrict__ out)
{
    __shared__ float4 sx[2 * CHUNK];   // 32KB: two float4 per opponent (duplicated)
    __shared__ float  red[THREADS];
    __shared__ int    slast;

    const int b   = blockIdx.y;
    const int dir = blockIdx.z;
    const float* __restrict__ qb = (dir == 0 ? preds : gts) + b * 3 * NN;
    const float* __restrict__ ob = (dir == 0 ? gts   : preds) + b * 3 * NN;

    const int tid = threadIdx.x;
    if (tid == 0) slast = 0;

    // Load queries, pack into f32x2 pairs
    float qx[Q], qy[Q], qz[Q];
    const int m0 = blockIdx.x * QTILE + tid;
#pragma unroll
    for (int q = 0; q < Q; q++) {
        const int m = m0 + q * THREADS;
        qx[q] = qb[m];
        qy[q] = qb[NN + m];
        qz[q] = qb[2 * NN + m];
    }
    const unsigned long long qx01 = pack2(qx[0], qx[1]), qx23 = pack2(qx[2], qx[3]);
    const unsigned long long qy01 = pack2(qy[0], qy[1]), qy23 = pack2(qy[2], qy[3]);
    const unsigned long long qz01 = pack2(qz[0], qz[1]), qz23 = pack2(qz[2], qz[3]);
    float mn0 = 3.4e38f, mn1 = 3.4e38f, mn2 = 3.4e38f, mn3 = 3.4e38f;

    for (int c = 0; c < NN; c += CHUNK) {
        __syncthreads();
        // Stage opponent chunk: coalesced per-channel loads, pre-scale by -2,
        // duplicate each component into both f32x2 lanes, norm into .w
        for (int i = tid; i < CHUNK; i += THREADS) {
            const int n = c + i;
            const float x0 = ob[n];
            const float x1 = ob[NN + n];
            const float x2 = ob[2 * NN + n];
            const float w  = x0 * x0 + x1 * x1 + x2 * x2;
            sx[2 * i]     = make_float4(-2.0f * x0, -2.0f * x0, -2.0f * x1, -2.0f * x1);
            sx[2 * i + 1] = make_float4(-2.0f * x2, -2.0f * x2, w, w);
        }
        __syncthreads();

        const ulonglong2* __restrict__ sp = (const ulonglong2*)sx;
#pragma unroll 4
        for (int i = 0; i < CHUNK; i++) {
            const ulonglong2 A = sp[2 * i];       // {px2, py2}  (LDS.128 broadcast)
            const ulonglong2 B = sp[2 * i + 1];   // {pz2, pw2}

            unsigned long long t0 = ffma2(B.x, qz01, B.y);
            t0 = ffma2(A.y, qy01, t0);
            t0 = ffma2(A.x, qx01, t0);
            min2(mn0, mn1, t0);

            unsigned long long t1 = ffma2(B.x, qz23, B.y);
            t1 = ffma2(A.y, qy23, t1);
            t1 = ffma2(A.x, qx23, t1);
            min2(mn2, mn3, t1);
        }
    }

    // Per-thread partial: sum of mins plus own squared norms (covers the
    // Sum(ry)/Sum(rx) terms exactly once across both directions).
    float s = mn0 + mn1 + mn2 + mn3;
#pragma unroll
    for (int q = 0; q < Q; q++)
        s += qx[q] * qx[q] + qy[q] * qy[q] + qz[q] * qz[q];

    // CTA tree reduction (deterministic)
    red[tid] = s;
    __syncthreads();
    for (int off = THREADS / 2; off > 0; off >>= 1) {
        if (tid < off) red[tid] += red[tid + off];
        __syncthreads();
    }

    const int cid = blockIdx.x + XTILES * (blockIdx.y + BB * blockIdx.z);
    if (tid == 0) {
        g_partials[cid] = red[0];
        __threadfence();
        const int old = atomicAdd(&g_count, 1);
        if (old == NCTAS - 1) slast = 1;
    }
    __syncthreads();

    // Last CTA: fold partials + KL, write the scalar, reset the ticket.
    if (slast) {
        __threadfence();
        float f = 0.0f;
        volatile const float* vp = g_partials;
        for (int i = tid; i < NCTAS; i += THREADS) f += vp[i];
        for (int i = tid; i < BB * ZZ; i += THREADS) {
            const float m  = mu[i];
            const float lv = logvar[i];
            f += -0.5f * (1.0f + lv - m * m - expf(lv));
        }
        red[tid] = f;
        __syncthreads();
        for (int off = THREADS / 2; off > 0; off >>= 1) {
            if (tid < off) red[tid] += red[tid + off];
            __syncthreads();
        }
        if (tid == 0) {
            out[0] = red[0];
            g_count = 0;   // reset for next graph replay (deterministic)
        }
    }
}

extern "C" void kernel_launch(void* const* d_in, const int* in_sizes, int n_in,
                              void* d_out, int out_size)
{
    const float* preds  = (const float*)d_in[0];   // [16, 3, 4096]
    const float* gts    = (const float*)d_in[1];   // [16, 3, 4096]
    const float* mu     = (const float*)d_in[2];   // [16, 128]
    const float* logvar = (const float*)d_in[3];   // [16, 128]
    float* out = (float*)d_out;

    dim3 grid(XTILES, BB, 2);
    chamfer_kernel<<<grid, THREADS>>>(preds, gts, mu, logvar, out);
}